// round 1
// baseline (speedup 1.0000x reference)
#include <cuda_runtime.h>
#include <math_constants.h>

#define BT   32
#define NPTS 128
#define DIM  64
#define AH   256

// ---------------- scratch (device globals; no allocations allowed) ----------------
__device__ float g_Wpe[64 * 256];      // (pm_w2^T @ am_w1^T): [k,c]
__device__ float g_biasTot[256];       // am_b1 + pm_b2 @ am_w1^T
__device__ float g_amw2t[256 * 64];    // am_w2 transposed: [c,d]
__device__ float g_a[BT * NPTS * 64];  // p @ pm_w1^T
__device__ float g_v[BT * NPTS * 64];  // v
__device__ float g_qa[BT * NPTS * 256]; // q @ am_w1^T
__device__ float g_ka[BT * NPTS * 256]; // k @ am_w1^T

// ---------------- weight prep: Wpe, biasTot, am_w2 transpose ----------------
__global__ void prep_weights(const float* __restrict__ pm_w2,
                             const float* __restrict__ am_w1,
                             const float* __restrict__ am_b1,
                             const float* __restrict__ pm_b2,
                             const float* __restrict__ am_w2) {
    int t = threadIdx.x;
    int b = blockIdx.x;
    if (b < 64) {
        // Wpe[b][t] = sum_d pm_w2[d][b] * am_w1[t][d]
        float s = 0.f;
        #pragma unroll
        for (int d = 0; d < 64; d++)
            s = fmaf(pm_w2[d * 64 + b], am_w1[t * 64 + d], s);
        g_Wpe[b * 256 + t] = s;
    } else if (b == 64) {
        float s = am_b1[t];
        #pragma unroll
        for (int d = 0; d < 64; d++)
            s = fmaf(pm_b2[d], am_w1[t * 64 + d], s);
        g_biasTot[t] = s;
    } else {
        // transpose am_w2 [64,256] -> g_amw2t [256,64]; block c = b-65, thread d
        int c = b - 65;
        if (t < 64) g_amw2t[c * 64 + t] = am_w2[t * 256 + c];
    }
}

// ---------------- per-point prep: p, a = p@pm_w1^T, v, qa, ka ----------------
__global__ void prep_rows(const float* __restrict__ x,
                          const float* __restrict__ pos,
                          const float* __restrict__ w_qkv,
                          const float* __restrict__ pm_w1,
                          const float* __restrict__ am_w1) {
    __shared__ float x_s[64];
    __shared__ float p_s[34];
    __shared__ float qk_s[128];
    int t   = threadIdx.x;
    int row = blockIdx.x;          // bt*128 + n
    int bt  = row >> 7;
    int n   = row & 127;

    if (t < 64) {
        x_s[t] = x[row * 64 + t];
    } else if (t < 98) {
        int f = t - 64;            // feature index = c*17 + j
        int c = f / 17, jj = f % 17;
        // pos layout [B,T,J,C,N]: bt*(17*3*128) + j*(3*128) + c*128 + n
        p_s[f] = pos[bt * 6528 + jj * 384 + c * 128 + n];
    }
    __syncthreads();

    if (t < 128) {                 // q rows 0..63, k rows 64..127 of w_qkv
        float s = 0.f;
        #pragma unroll
        for (int m = 0; m < 64; m++) s = fmaf(x_s[m], w_qkv[t * 64 + m], s);
        qk_s[t] = s;
    } else if (t < 192) {          // v
        int dd = t - 128;
        float s = 0.f;
        #pragma unroll
        for (int m = 0; m < 64; m++) s = fmaf(x_s[m], w_qkv[(128 + dd) * 64 + m], s);
        g_v[row * 64 + dd] = s;
    } else {                       // a = p @ pm_w1^T
        int kk = t - 192;
        float s = 0.f;
        #pragma unroll
        for (int f = 0; f < 34; f++) s = fmaf(p_s[f], pm_w1[kk * 34 + f], s);
        g_a[row * 64 + kk] = s;
    }
    __syncthreads();

    {
        float sq = 0.f, sk = 0.f;
        #pragma unroll
        for (int dd = 0; dd < 64; dd++) {
            float w = am_w1[t * 64 + dd];
            sq = fmaf(qk_s[dd], w, sq);
            sk = fmaf(qk_s[64 + dd], w, sk);
        }
        g_qa[row * 256 + t] = sq;
        g_ka[row * 256 + t] = sk;
    }
}

// ---------------- main fused pair kernel with online softmax ----------------
// One CTA per (bt, i); 256 threads. Weights live in registers; smem carries
// broadcast vectors (r, h) and cross-thread reduction staging only.
__global__ __launch_bounds__(256, 1)
void pt_main(const float* __restrict__ pm_b1,
             const float* __restrict__ pm_w2,
             const float* __restrict__ pm_b2,
             const float* __restrict__ am_b2,
             float* __restrict__ out) {
    __shared__ __align__(16) float r_s[64];
    __shared__ __align__(16) float h_s[256];
    __shared__ float e_part[256];
    __shared__ float o_part[256];
    __shared__ float a_i_s[64];
    __shared__ float qa_i_s[256];
    __shared__ float pm_b1_s[64];
    __shared__ float biasTot_s[256];

    const int t    = threadIdx.x;
    const int i    = blockIdx.x;
    const int bt   = blockIdx.y;
    const int rowi = bt * NPTS + i;
    const int d    = t & 63;
    const int part = t >> 6;

    qa_i_s[t]    = g_qa[rowi * 256 + t];
    biasTot_s[t] = g_biasTot[t];
    if (t < 64) {
        a_i_s[t]   = g_a[rowi * 64 + t];
        pm_b1_s[t] = pm_b1[t];
    }

    // per-thread register-resident weights
    float wpe[64];
    #pragma unroll
    for (int k = 0; k < 64; k++) wpe[k] = g_Wpe[k * 256 + t];
    float aw[64];
    #pragma unroll
    for (int c = 0; c < 64; c++) aw[c] = g_amw2t[(part * 64 + c) * 64 + d];
    float pw[16];
    #pragma unroll
    for (int k = 0; k < 16; k++) pw[k] = pm_w2[d * 64 + part * 16 + k];

    float m = -CUDART_INF_F, l = 0.f, acc = 0.f;
    float amb2 = 0.f, pmb2 = 0.f;
    if (t < 64) { amb2 = am_b2[t]; pmb2 = pm_b2[t]; }

    const int base = bt * NPTS;
    float ka_cur = g_ka[base * 256 + t];
    float aj_cur = 0.f, vj_cur = 0.f;
    if (t < 64) {
        aj_cur = g_a[base * 64 + t];
        vj_cur = g_v[base * 64 + t];
    }
    __syncthreads();

    for (int j = 0; j < NPTS; j++) {
        // software prefetch next j's global rows (hide L2 latency)
        float ka_nx = 0.f, aj_nx = 0.f, vj_nx = 0.f;
        if (j + 1 < NPTS) {
            ka_nx = g_ka[(base + j + 1) * 256 + t];
            if (t < 64) {
                aj_nx = g_a[(base + j + 1) * 64 + t];
                vj_nx = g_v[(base + j + 1) * 64 + t];
            }
        }

        // r = relu(a_i - a_j + pm_b1)
        if (t < 64) r_s[t] = fmaxf(a_i_s[t] - aj_cur + pm_b1_s[t], 0.f);
        __syncthreads();

        // h[c] = relu(qa_i[c] - ka_j[c] + biasTot[c] + r @ Wpe[:,c])
        float hp = qa_i_s[t] - ka_cur + biasTot_s[t];
        const float4* r4 = (const float4*)r_s;
        #pragma unroll
        for (int k4 = 0; k4 < 16; k4++) {
            float4 r = r4[k4];
            hp = fmaf(r.x, wpe[4 * k4 + 0], hp);
            hp = fmaf(r.y, wpe[4 * k4 + 1], hp);
            hp = fmaf(r.z, wpe[4 * k4 + 2], hp);
            hp = fmaf(r.w, wpe[4 * k4 + 3], hp);
        }
        h_s[t] = fmaxf(hp, 0.f);

        // e partial: thread (d,part) covers k in [part*16, part*16+16)
        float ep = 0.f;
        const float4* rp4 = (const float4*)(r_s + part * 16);
        #pragma unroll
        for (int k4 = 0; k4 < 4; k4++) {
            float4 r = rp4[k4];
            ep = fmaf(r.x, pw[4 * k4 + 0], ep);
            ep = fmaf(r.y, pw[4 * k4 + 1], ep);
            ep = fmaf(r.z, pw[4 * k4 + 2], ep);
            ep = fmaf(r.w, pw[4 * k4 + 3], ep);
        }
        e_part[t] = ep;
        __syncthreads();

        // o partial: thread (d,part) covers c in [part*64, part*64+64)
        float op = 0.f;
        const float4* h4 = (const float4*)(h_s + part * 64);
        #pragma unroll
        for (int c4 = 0; c4 < 16; c4++) {
            float4 hv = h4[c4];
            op = fmaf(hv.x, aw[4 * c4 + 0], op);
            op = fmaf(hv.y, aw[4 * c4 + 1], op);
            op = fmaf(hv.z, aw[4 * c4 + 2], op);
            op = fmaf(hv.w, aw[4 * c4 + 3], op);
        }
        o_part[t] = op;
        __syncthreads();

        // reduce + online softmax (threads 0..63 own channel d = t)
        if (t < 64) {
            float o = o_part[t] + o_part[64 + t] + o_part[128 + t] + o_part[192 + t] + amb2;
            float e = e_part[t] + e_part[64 + t] + e_part[128 + t] + e_part[192 + t] + pmb2;
            float val = vj_cur + e;
            float mn  = fmaxf(m, o);
            float sc  = __expf(m - mn);
            float pwr = __expf(o - mn);
            l   = l * sc + pwr;
            acc = acc * sc + pwr * val;
            m   = mn;
        }
        ka_cur = ka_nx; aj_cur = aj_nx; vj_cur = vj_nx;
        // next iteration's first smem write (r_s, by t<64) is ordered after the
        // t<64 reads above; other threads' writes (h_s/e_part) come after the
        // next __syncthreads() inside the loop. 3 barriers/iter suffice.
    }

    if (t < 64) out[rowi * 64 + t] = acc / l;
}

// ---------------- launch ----------------
extern "C" void kernel_launch(void* const* d_in, const int* in_sizes, int n_in,
                              void* d_out, int out_size) {
    const float* x      = (const float*)d_in[0];
    const float* pos    = (const float*)d_in[1];
    const float* w_qkv  = (const float*)d_in[2];
    const float* pm_w1  = (const float*)d_in[3];
    const float* pm_b1  = (const float*)d_in[4];
    const float* pm_w2  = (const float*)d_in[5];
    const float* pm_b2  = (const float*)d_in[6];
    const float* am_w1  = (const float*)d_in[7];
    const float* am_b1  = (const float*)d_in[8];
    const float* am_w2  = (const float*)d_in[9];
    const float* am_b2  = (const float*)d_in[10];
    float* out = (float*)d_out;

    prep_weights<<<321, 256>>>(pm_w2, am_w1, am_b1, pm_b2, am_w2);
    prep_rows<<<BT * NPTS, 256>>>(x, pos, w_qkv, pm_w1, am_w1);
    pt_main<<<dim3(NPTS, BT), 256>>>(pm_b1, pm_w2, pm_b2, am_b2, out);
}

// round 2
// speedup vs baseline: 2.4705x; 2.4705x over previous
#include <cuda_runtime.h>
#include <math_constants.h>

#define BT   32
#define NPTS 128
#define DIM  64
#define AH   256

// ---------------- scratch (device globals; no allocations allowed) ----------------
__device__ float g_Wpe[64 * 256];       // (pm_w2^T @ am_w1^T): [k][c]
__device__ float g_biasTot[256];        // am_b1 + pm_b2 @ am_w1^T
__device__ float g_amw2t[256 * 64];     // am_w2 transposed: [c][d]
__device__ float g_a[BT * NPTS * 64];   // p @ pm_w1^T
__device__ float g_v[BT * NPTS * 64];   // v
__device__ float g_qa[BT * NPTS * 256]; // q @ am_w1^T
__device__ float g_ka[BT * NPTS * 256]; // k @ am_w1^T

// ---------------- packed fp32x2 helpers (Blackwell FFMA2 path) ----------------
__device__ __forceinline__ unsigned long long pack2(float x) {
    unsigned long long r;
    asm("mov.b64 %0, {%1, %1};" : "=l"(r) : "f"(x));
    return r;
}
__device__ __forceinline__ void ffma2(unsigned long long& d, unsigned long long a,
                                      unsigned long long b) {
    asm("fma.rn.f32x2 %0, %1, %2, %0;" : "+l"(d) : "l"(a), "l"(b));
}
__device__ __forceinline__ float2 unpack2(unsigned long long v) {
    float2 f;
    asm("mov.b64 {%0, %1}, %2;" : "=f"(f.x), "=f"(f.y) : "l"(v));
    return f;
}

// ---------------- weight prep: Wpe, biasTot, am_w2 transpose ----------------
__global__ void prep_weights(const float* __restrict__ pm_w2,
                             const float* __restrict__ am_w1,
                             const float* __restrict__ am_b1,
                             const float* __restrict__ pm_b2,
                             const float* __restrict__ am_w2) {
    int t = threadIdx.x;
    int b = blockIdx.x;
    if (b < 64) {
        float s = 0.f;
        #pragma unroll
        for (int d = 0; d < 64; d++)
            s = fmaf(pm_w2[d * 64 + b], am_w1[t * 64 + d], s);
        g_Wpe[b * 256 + t] = s;
    } else if (b == 64) {
        float s = am_b1[t];
        #pragma unroll
        for (int d = 0; d < 64; d++)
            s = fmaf(pm_b2[d], am_w1[t * 64 + d], s);
        g_biasTot[t] = s;
    } else {
        int c = b - 65;
        if (t < 64) g_amw2t[c * 64 + t] = am_w2[t * 256 + c];
    }
}

// ---------------- per-point prep: a = p@pm_w1^T, v, qa, ka ----------------
__global__ void prep_rows(const float* __restrict__ x,
                          const float* __restrict__ pos,
                          const float* __restrict__ w_qkv,
                          const float* __restrict__ pm_w1,
                          const float* __restrict__ am_w1) {
    __shared__ float x_s[64];
    __shared__ float p_s[34];
    __shared__ float qk_s[128];
    int t   = threadIdx.x;
    int row = blockIdx.x;          // bt*128 + n
    int bt  = row >> 7;
    int n   = row & 127;

    if (t < 64) {
        x_s[t] = x[row * 64 + t];
    } else if (t < 98) {
        int f = t - 64;            // feature = c*17 + j
        int c = f / 17, jj = f % 17;
        p_s[f] = pos[bt * 6528 + jj * 384 + c * 128 + n];
    }
    __syncthreads();

    if (t < 128) {                 // q rows 0..63, k rows 64..127
        float s = 0.f;
        #pragma unroll
        for (int m = 0; m < 64; m++) s = fmaf(x_s[m], w_qkv[t * 64 + m], s);
        qk_s[t] = s;
    } else if (t < 192) {          // v
        int dd = t - 128;
        float s = 0.f;
        #pragma unroll
        for (int m = 0; m < 64; m++) s = fmaf(x_s[m], w_qkv[(128 + dd) * 64 + m], s);
        g_v[row * 64 + dd] = s;
    } else {                       // a = p @ pm_w1^T
        int kk = t - 192;
        float s = 0.f;
        #pragma unroll
        for (int f = 0; f < 34; f++) s = fmaf(p_s[f], pm_w1[kk * 34 + f], s);
        g_a[row * 64 + kk] = s;
    }
    __syncthreads();

    {
        float sq = 0.f, sk = 0.f;
        #pragma unroll
        for (int dd = 0; dd < 64; dd++) {
            float w = am_w1[t * 64 + dd];
            sq = fmaf(qk_s[dd], w, sq);
            sk = fmaf(qk_s[64 + dd], w, sk);
        }
        g_qa[row * 256 + t] = sq;
        g_ka[row * 256 + t] = sk;
    }
}

// ---------------- main kernel: 3 register-tiled GEMMs + parallel softmax ----------------
// One CTA per (bt, i). 256 threads. All 128 j processed as batch GEMMs:
//   R[128,64]  = relu(a_i + b1 - a_j)                 (smem)
//   H[128,256] = relu(qa_i + biasTot - ka_j + R@Wpe)  (smem, packed f32x2 GEMM)
//   E[128,64]  = R@pm_w2^T (+pm_b2 +v -> val, regs)
//   O[128,64]  = H@am_w2t (+am_b2)                    (smem, packed f32x2 GEMM)
//   out[i,d]   = softmax_j(O[:,d]) . val[:,d]
#define SMEM_FLOATS 57664   // 230656 bytes

__global__ __launch_bounds__(256)
void pt_main(const float* __restrict__ pm_b1,
             const float* __restrict__ pm_w2,
             const float* __restrict__ pm_b2,
             const float* __restrict__ am_b2,
             float* __restrict__ out) {
    extern __shared__ float smem[];
    float* h_s  = smem;            // [128][256] H (also softmax partials at end)
    float* W_s  = smem + 32768;    // [64][256] Wpe, then [256][64] am_w2t
    float* R_s  = smem + 49152;    // [128][64] R, then O
    float* qb_s = smem + 57344;    // [256] qa_i + biasTot
    float* ab_s = smem + 57600;    // [64]  a_i + pm_b1

    const int t    = threadIdx.x;
    const int i    = blockIdx.x;
    const int bt   = blockIdx.y;
    const int rowi = bt * NPTS + i;
    const int base = bt * NPTS;

    // ---- P1a: per-i vectors + Wpe -> smem ----
    if (t < 64) ab_s[t] = g_a[rowi * 64 + t] + pm_b1[t];
    qb_s[t] = g_qa[rowi * 256 + t] + g_biasTot[t];
    {
        const float4* src = (const float4*)g_Wpe;
        float4*       dst = (float4*)W_s;
        #pragma unroll
        for (int q = 0; q < 16; q++) dst[q * 256 + t] = src[q * 256 + t];
    }
    __syncthreads();

    // ---- P1b: R = relu(ab_i - a_j) ----
    #pragma unroll
    for (int q = 0; q < 32; q++) {
        int idx = q * 256 + t;
        int j = idx >> 6, k = idx & 63;
        R_s[idx] = fmaxf(ab_s[k] - g_a[(base + j) * 64 + k], 0.f);
    }
    __syncthreads();

    // ---- P2: GEMM1  H = relu(qb - ka + R @ Wpe) ----
    // thread tile: 8 j (jg = t/16) x 16 c as 8 pairs at c = pp*32 + cg*2 (cg = t%16)
    const int jg = t >> 4;
    const int cg = t & 15;
    {
        unsigned long long acc[8][8];
        #pragma unroll
        for (int a_ = 0; a_ < 8; a_++)
            #pragma unroll
            for (int b_ = 0; b_ < 8; b_++) acc[a_][b_] = 0ull;

        for (int k4 = 0; k4 < 16; k4++) {
            float4 rv[8];
            #pragma unroll
            for (int jj = 0; jj < 8; jj++)
                rv[jj] = *(const float4*)&R_s[(jg * 8 + jj) * 64 + k4 * 4];
            #pragma unroll
            for (int kk = 0; kk < 4; kk++) {
                const float* wrow = &W_s[(k4 * 4 + kk) * 256 + cg * 2];
                unsigned long long w[8];
                #pragma unroll
                for (int pp = 0; pp < 8; pp++)
                    w[pp] = *(const unsigned long long*)(wrow + pp * 32);
                #pragma unroll
                for (int jj = 0; jj < 8; jj++) {
                    float rs = (kk == 0) ? rv[jj].x : (kk == 1) ? rv[jj].y
                             : (kk == 2) ? rv[jj].z : rv[jj].w;
                    unsigned long long r2 = pack2(rs);
                    #pragma unroll
                    for (int pp = 0; pp < 8; pp++) ffma2(acc[jj][pp], r2, w[pp]);
                }
            }
        }
        // add (qb - ka), relu, store H
        #pragma unroll
        for (int jj = 0; jj < 8; jj++) {
            int j = jg * 8 + jj;
            const float* karow = &g_ka[(base + j) * 256 + cg * 2];
            float*       hrow  = &h_s[j * 256 + cg * 2];
            const float* qbrow = &qb_s[cg * 2];
            #pragma unroll
            for (int pp = 0; pp < 8; pp++) {
                float2 ka = *(const float2*)(karow + pp * 32);
                float2 qb = *(const float2*)(qbrow + pp * 32);
                float2 hv = unpack2(acc[jj][pp]);
                hv.x = fmaxf(qb.x - ka.x + hv.x, 0.f);
                hv.y = fmaxf(qb.y - ka.y + hv.y, 0.f);
                *(float2*)(hrow + pp * 32) = hv;
            }
        }
    }
    __syncthreads();

    // ---- P3: am_w2t -> smem (overwrites Wpe); eGEMM val = R@pm_w2^T + pm_b2 + v ----
    {
        const float4* src = (const float4*)g_amw2t;
        float4*       dst = (float4*)W_s;
        #pragma unroll
        for (int q = 0; q < 16; q++) dst[q * 256 + t] = src[q * 256 + t];
    }
    const int d  = t & 63;
    const int jq = t >> 6;
    float val[32];
    {
        float pw[64];
        const float4* pwsrc = (const float4*)(pm_w2 + d * 64);
        #pragma unroll
        for (int q = 0; q < 16; q++) {
            float4 v4 = pwsrc[q];
            pw[q * 4] = v4.x; pw[q * 4 + 1] = v4.y;
            pw[q * 4 + 2] = v4.z; pw[q * 4 + 3] = v4.w;
        }
        #pragma unroll
        for (int jj = 0; jj < 32; jj++) val[jj] = 0.f;
        for (int k4 = 0; k4 < 16; k4++) {
            #pragma unroll
            for (int jj = 0; jj < 32; jj++) {
                float4 r = *(const float4*)&R_s[(jq * 32 + jj) * 64 + k4 * 4];
                val[jj] = fmaf(r.x, pw[k4 * 4],     val[jj]);
                val[jj] = fmaf(r.y, pw[k4 * 4 + 1], val[jj]);
                val[jj] = fmaf(r.z, pw[k4 * 4 + 2], val[jj]);
                val[jj] = fmaf(r.w, pw[k4 * 4 + 3], val[jj]);
            }
        }
        float pb = pm_b2[d];
        #pragma unroll
        for (int jj = 0; jj < 32; jj++)
            val[jj] += pb + g_v[(base + jq * 32 + jj) * 64 + d];
    }
    __syncthreads();   // all R reads done; W_s now am_w2t

    // ---- P4: GEMM2  O = H @ am_w2t (+am_b2); store O into R_s region ----
    // thread tile: 8 j (jg) x 4 d as 2 pairs at d = p*32 + dg*2 (dg = t%16)
    {
        const int dg = cg;
        unsigned long long oacc[8][2];
        #pragma unroll
        for (int a_ = 0; a_ < 8; a_++) { oacc[a_][0] = 0ull; oacc[a_][1] = 0ull; }

        for (int c = 0; c < 256; c += 2) {
            const float* w0 = &W_s[c * 64 + dg * 2];
            unsigned long long w0a = *(const unsigned long long*)(w0);
            unsigned long long w0b = *(const unsigned long long*)(w0 + 32);
            unsigned long long w1a = *(const unsigned long long*)(w0 + 64);
            unsigned long long w1b = *(const unsigned long long*)(w0 + 96);
            #pragma unroll
            for (int jj = 0; jj < 8; jj++) {
                float2 hv = *(const float2*)&h_s[(jg * 8 + jj) * 256 + c];
                unsigned long long h0 = pack2(hv.x);
                unsigned long long h1 = pack2(hv.y);
                ffma2(oacc[jj][0], h0, w0a);
                ffma2(oacc[jj][1], h0, w0b);
                ffma2(oacc[jj][0], h1, w1a);
                ffma2(oacc[jj][1], h1, w1b);
            }
        }
        float* o_s = R_s;
        float2 b2a = *(const float2*)&am_b2[dg * 2];
        float2 b2b = *(const float2*)&am_b2[32 + dg * 2];
        #pragma unroll
        for (int jj = 0; jj < 8; jj++) {
            int j = jg * 8 + jj;
            float2 p0 = unpack2(oacc[jj][0]);
            float2 p1 = unpack2(oacc[jj][1]);
            p0.x += b2a.x; p0.y += b2a.y;
            p1.x += b2b.x; p1.y += b2b.y;
            *(float2*)&o_s[j * 64 + dg * 2]      = p0;
            *(float2*)&o_s[j * 64 + 32 + dg * 2] = p1;
        }
    }
    __syncthreads();

    // ---- P5: softmax over j (4-way split per d), combine, write out ----
    {
        const float* o_s = R_s;
        float ov[32];
        #pragma unroll
        for (int jj = 0; jj < 32; jj++) ov[jj] = o_s[(jq * 32 + jj) * 64 + d];
        float m = ov[0];
        #pragma unroll
        for (int jj = 1; jj < 32; jj++) m = fmaxf(m, ov[jj]);
        float l = 0.f, a = 0.f;
        #pragma unroll
        for (int jj = 0; jj < 32; jj++) {
            float p = __expf(ov[jj] - m);
            l += p;
            a = fmaf(p, val[jj], a);
        }
        float* pm_ = h_s;
        float* pl_ = h_s + 256;
        float* pa_ = h_s + 512;
        pm_[jq * 64 + d] = m;
        pl_[jq * 64 + d] = l;
        pa_[jq * 64 + d] = a;
        __syncthreads();
        if (t < 64) {
            float m0 = pm_[t], m1 = pm_[64 + t], m2 = pm_[128 + t], m3 = pm_[192 + t];
            float M  = fmaxf(fmaxf(m0, m1), fmaxf(m2, m3));
            float e0 = __expf(m0 - M), e1 = __expf(m1 - M);
            float e2 = __expf(m2 - M), e3 = __expf(m3 - M);
            float L = pl_[t] * e0 + pl_[64 + t] * e1 + pl_[128 + t] * e2 + pl_[192 + t] * e3;
            float A = pa_[t] * e0 + pa_[64 + t] * e1 + pa_[128 + t] * e2 + pa_[192 + t] * e3;
            out[rowi * 64 + t] = A / L;
        }
    }
}

// ---------------- launch ----------------
extern "C" void kernel_launch(void* const* d_in, const int* in_sizes, int n_in,
                              void* d_out, int out_size) {
    const float* x      = (const float*)d_in[0];
    const float* pos    = (const float*)d_in[1];
    const float* w_qkv  = (const float*)d_in[2];
    const float* pm_w1  = (const float*)d_in[3];
    const float* pm_b1  = (const float*)d_in[4];
    const float* pm_w2  = (const float*)d_in[5];
    const float* pm_b2  = (const float*)d_in[6];
    const float* am_w1  = (const float*)d_in[7];
    const float* am_b1  = (const float*)d_in[8];
    const float* am_w2  = (const float*)d_in[9];
    const float* am_b2  = (const float*)d_in[10];
    float* out = (float*)d_out;

    static bool attr_set = false;
    if (!attr_set) {
        cudaFuncSetAttribute(pt_main, cudaFuncAttributeMaxDynamicSharedMemorySize,
                             SMEM_FLOATS * sizeof(float));
        attr_set = true;
    }

    prep_weights<<<321, 256>>>(pm_w2, am_w1, am_b1, pm_b2, am_w2);
    prep_rows<<<BT * NPTS, 256>>>(x, pos, w_qkv, pm_w1, am_w1);
    pt_main<<<dim3(NPTS, BT), 256, SMEM_FLOATS * sizeof(float)>>>(pm_b1, pm_w2, pm_b2,
                                                                  am_b2, out);
}

// round 12
// speedup vs baseline: 4.3135x; 1.7460x over previous
#include <cuda_runtime.h>
#include <cuda_fp16.h>
#include <cstdint>

#define BT   32
#define NPTS 128

// ---------------- mma/ldmatrix helpers (portable PTX, sm_80+) ----------------
__device__ __forceinline__ uint32_t smem_u32(const void* p) {
    uint32_t a;
    asm("{ .reg .u64 t; cvta.to.shared.u64 t, %1; cvt.u32.u64 %0, t; }" : "=r"(a) : "l"(p));
    return a;
}
__device__ __forceinline__ void ldsm_x4(uint32_t& r0, uint32_t& r1, uint32_t& r2,
                                        uint32_t& r3, uint32_t addr) {
    asm volatile("ldmatrix.sync.aligned.m8n8.x4.shared.b16 {%0,%1,%2,%3}, [%4];"
                 : "=r"(r0), "=r"(r1), "=r"(r2), "=r"(r3) : "r"(addr));
}
__device__ __forceinline__ void ldsm_x2(uint32_t& r0, uint32_t& r1, uint32_t addr) {
    asm volatile("ldmatrix.sync.aligned.m8n8.x2.shared.b16 {%0,%1}, [%2];"
                 : "=r"(r0), "=r"(r1) : "r"(addr));
}
__device__ __forceinline__ void mma16816(float* c, const uint32_t* a, const uint32_t* b) {
    asm volatile("mma.sync.aligned.m16n8k16.row.col.f32.f16.f16.f32 "
                 "{%0,%1,%2,%3}, {%4,%5,%6,%7}, {%8,%9}, {%0,%1,%2,%3};"
                 : "+f"(c[0]), "+f"(c[1]), "+f"(c[2]), "+f"(c[3])
                 : "r"(a[0]), "r"(a[1]), "r"(a[2]), "r"(a[3]), "r"(b[0]), "r"(b[1]));
}
__device__ __forceinline__ uint32_t pack_h2(__half x, __half y) {
    __half2 h = __halves2half2(x, y);
    return *(uint32_t*)&h;
}
__device__ __forceinline__ void split2(float x, float y, uint32_t& hi, uint32_t& lo) {
    __half hx = __float2half_rn(x), hy = __float2half_rn(y);
    hi = pack_h2(hx, hy);
    lo = pack_h2(__float2half_rn(x - __half2float(hx)),
                 __float2half_rn(y - __half2float(hy)));
}

// ---------------- device globals ----------------
__device__ float g_Wpe[64 * 256];
__device__ float g_biasTot[256];
__device__ float g_a[BT * NPTS * 64];
__device__ float g_q[BT * NPTS * 64];
__device__ float g_k[BT * NPTS * 64];
__device__ float g_v[BT * NPTS * 64];
// fp16 hi/lo weight images, padded row strides for conflict-free ldmatrix
__device__ __align__(16) __half g_W1h[256 * 136];  // [c][k] k=0..127, stride 136
__device__ __align__(16) __half g_W1l[256 * 136];
__device__ __align__(16) __half g_W2h[64 * 264];   // [d][c] c=0..255, stride 264
__device__ __align__(16) __half g_W2l[64 * 264];
__device__ __align__(16) __half g_B3h[64 * 72];    // [d][k] k=0..63,  stride 72
__device__ __align__(16) __half g_B3l[64 * 72];

// ---------------- prep kernels ----------------
__global__ void prep_weights1(const float* __restrict__ pm_w2,
                              const float* __restrict__ am_w1,
                              const float* __restrict__ am_b1,
                              const float* __restrict__ pm_b2) {
    int t = threadIdx.x, b = blockIdx.x;
    if (b < 64) {
        float s = 0.f;
        #pragma unroll
        for (int d = 0; d < 64; d++)
            s = fmaf(pm_w2[d * 64 + b], am_w1[t * 64 + d], s);
        g_Wpe[b * 256 + t] = s;
    } else {
        float s = am_b1[t];
        #pragma unroll
        for (int d = 0; d < 64; d++)
            s = fmaf(pm_b2[d], am_w1[t * 64 + d], s);
        g_biasTot[t] = s;
    }
}

__global__ void prep_weights2(const float* __restrict__ am_w1,
                              const float* __restrict__ am_w2,
                              const float* __restrict__ pm_w2) {
    int idx = blockIdx.x * 256 + threadIdx.x;
    float v; int off; __half *ph, *pl;
    if (idx < 32768) {                       // W1 [c][k]: k<64 = Wpe^T, k>=64 = am_w1
        int c = idx >> 7, k = idx & 127;
        v = (k < 64) ? g_Wpe[k * 256 + c] : am_w1[c * 64 + (k - 64)];
        off = c * 136 + k;
        ph = g_W1h; pl = g_W1l;
    } else if (idx < 49152) {                // W2 = am_w2 [d][c]
        int r = idx - 32768, d = r >> 8, c = r & 255;
        v = am_w2[d * 256 + c];
        off = d * 264 + c;
        ph = g_W2h; pl = g_W2l;
    } else if (idx < 53248) {                // B3 = pm_w2 [d][k]
        int r = idx - 49152, d = r >> 6, k = r & 63;
        v = pm_w2[d * 64 + k];
        off = d * 72 + k;
        ph = g_B3h; pl = g_B3l;
    } else return;
    __half h = __float2half_rn(v);
    ph[off] = h;
    pl[off] = __float2half_rn(v - __half2float(h));
}

__global__ void prep_rows(const float* __restrict__ x,
                          const float* __restrict__ pos,
                          const float* __restrict__ w_qkv,
                          const float* __restrict__ pm_w1) {
    __shared__ float x_s[64];
    __shared__ float p_s[34];
    int t = threadIdx.x, row = blockIdx.x;
    int bt = row >> 7, n = row & 127;
    if (t < 64) x_s[t] = x[row * 64 + t];
    else if (t < 98) {
        int f = t - 64, c = f / 17, jj = f % 17;
        p_s[f] = pos[bt * 6528 + jj * 384 + c * 128 + n];
    }
    __syncthreads();
    if (t < 192) {
        float s = 0.f;
        #pragma unroll
        for (int m = 0; m < 64; m++) s = fmaf(x_s[m], w_qkv[t * 64 + m], s);
        if (t < 64)       g_q[row * 64 + t] = s;
        else if (t < 128) g_k[row * 64 + t - 64] = s;
        else              g_v[row * 64 + t - 128] = s;
    } else {
        int kk = t - 192;
        float s = 0.f;
        #pragma unroll
        for (int f = 0; f < 34; f++) s = fmaf(p_s[f], pm_w1[kk * 34 + f], s);
        g_a[row * 64 + kk] = s;
    }
}

// ---------------- smem layout (bytes) ----------------
#define OFF_A1H   0                 // [128][136] fp16 (34816)
#define OFF_A1L   34816
#define OFF_W2H   0                 // alias after GEMM1/eGEMM (33792)
#define OFF_W2L   34816
#define OFF_W1H   69632             // [256][136] fp16 (69632)
#define OFF_W1L   139264
#define OFF_B3H   208896            // [64][72] fp16 (9216)
#define OFF_B3L   218112
#define OFF_BIAS  227328            // 256 f32
#define OFF_RED   228352            // 3*256 f32
#define SMEM_TOTAL 231424
#define OFF_OS    69632             // alias: O [64][136] f32 (34816)
#define OFF_VS    104448            // alias: val [64][136] f32

__global__ __launch_bounds__(256)
void pt_main(const float* __restrict__ pm_b1,
             const float* __restrict__ pm_b2,
             const float* __restrict__ am_b2,
             float* __restrict__ out) {
    extern __shared__ char smem[];
    const uint32_t sb = smem_u32(smem);
    const int t = threadIdx.x;
    const int w = t >> 5, lane = t & 31;
    const int i = blockIdx.x, bt = blockIdx.y;
    const int rowi = bt * NPTS + i, base = bt * NPTS;

    // ---- phase 0: copy W1, B3, bias; build A1 = [R | q-k] hi/lo ----
    {
        const float4* s; float4* d;
        // W1h/W1l: 256*136 halfs = 69632 B = 4352 float4 = 17 * 256 (exact)
        s = (const float4*)g_W1h; d = (float4*)(smem + OFF_W1H);
        #pragma unroll
        for (int q = 0; q < 17; q++) d[q * 256 + t] = s[q * 256 + t];
        s = (const float4*)g_W1l; d = (float4*)(smem + OFF_W1L);
        #pragma unroll
        for (int q = 0; q < 17; q++) d[q * 256 + t] = s[q * 256 + t];
        // B3h/B3l: 64*72 halfs = 9216 B = 576 float4 = 2*256 + 64
        s = (const float4*)g_B3h; d = (float4*)(smem + OFF_B3H);
        #pragma unroll
        for (int q = 0; q < 2; q++) d[q * 256 + t] = s[q * 256 + t];
        if (t < 64) d[512 + t] = s[512 + t];
        s = (const float4*)g_B3l; d = (float4*)(smem + OFF_B3L);
        #pragma unroll
        for (int q = 0; q < 2; q++) d[q * 256 + t] = s[q * 256 + t];
        if (t < 64) d[512 + t] = s[512 + t];
        ((float*)(smem + OFF_BIAS))[t] = g_biasTot[t];
    }
    {
        const int j = t >> 1, kh = (t & 1) * 32;
        const float4* aj = (const float4*)(g_a + (base + j) * 64 + kh);
        const float4* ai = (const float4*)(g_a + rowi * 64 + kh);
        const float4* b1 = (const float4*)(pm_b1 + kh);
        const float4* kj = (const float4*)(g_k + (base + j) * 64 + kh);
        const float4* qi = (const float4*)(g_q + rowi * 64 + kh);
        __half* A1H = (__half*)(smem + OFF_A1H);
        __half* A1L = (__half*)(smem + OFF_A1L);
        #pragma unroll
        for (int c4 = 0; c4 < 8; c4++) {
            float4 av = aj[c4], iv = ai[c4], bv = b1[c4];
            float r0 = fmaxf(iv.x + bv.x - av.x, 0.f);
            float r1 = fmaxf(iv.y + bv.y - av.y, 0.f);
            float r2 = fmaxf(iv.z + bv.z - av.z, 0.f);
            float r3 = fmaxf(iv.w + bv.w - av.w, 0.f);
            int o = j * 136 + kh + c4 * 4;
            uint32_t hi, lo;
            split2(r0, r1, hi, lo);
            *(uint32_t*)(A1H + o) = hi;  *(uint32_t*)(A1L + o) = lo;
            split2(r2, r3, hi, lo);
            *(uint32_t*)(A1H + o + 2) = hi;  *(uint32_t*)(A1L + o + 2) = lo;
            float4 kv = kj[c4], qv = qi[c4];
            int oq = o + 64;
            split2(qv.x - kv.x, qv.y - kv.y, hi, lo);
            *(uint32_t*)(A1H + oq) = hi;  *(uint32_t*)(A1L + oq) = lo;
            split2(qv.z - kv.z, qv.w - kv.w, hi, lo);
            *(uint32_t*)(A1H + oq + 2) = hi;  *(uint32_t*)(A1L + oq + 2) = lo;
        }
    }
    __syncthreads();

    // ldmatrix address lanes
    const int arow = w * 16 + (lane & 15);
    const int asel = (lane >> 4) << 3;          // 0 / 8 halfs (k half)
    const int brow = lane & 7;
    const int bsel = ((lane >> 3) & 1) << 3;

    // ---- GEMM1: acc[32][4] = A1(K=128) @ W1^T, 3-pass hi/lo ----
    float acc[32][4];
    #pragma unroll
    for (int cb = 0; cb < 32; cb++)
        #pragma unroll
        for (int e = 0; e < 4; e++) acc[cb][e] = 0.f;
    for (int ks = 0; ks < 8; ks++) {
        uint32_t ah[4], al[4];
        uint32_t aa = sb + OFF_A1H + (uint32_t)(arow * 136 + ks * 16 + asel) * 2;
        ldsm_x4(ah[0], ah[1], ah[2], ah[3], aa);
        aa = sb + OFF_A1L + (uint32_t)(arow * 136 + ks * 16 + asel) * 2;
        ldsm_x4(al[0], al[1], al[2], al[3], aa);
        #pragma unroll
        for (int cb = 0; cb < 32; cb++) {
            uint32_t bh[2], bl[2];
            uint32_t ba = (uint32_t)((cb * 8 + brow) * 136 + ks * 16 + bsel) * 2;
            ldsm_x2(bh[0], bh[1], sb + OFF_W1H + ba);
            ldsm_x2(bl[0], bl[1], sb + OFF_W1L + ba);
            mma16816(acc[cb], ah, bh);
            mma16816(acc[cb], ah, bl);
            mma16816(acc[cb], al, bh);
        }
    }

    // ---- H = relu(acc + biasTot) -> register A-fragments hi/lo ----
    const int cn = (lane & 3) * 2;
    uint32_t Hh[16][4], Hl[16][4];
    {
        const float* biasS = (const float*)(smem + OFF_BIAS);
        #pragma unroll
        for (int ks2 = 0; ks2 < 16; ks2++) {
            #pragma unroll
            for (int hf = 0; hf < 2; hf++) {
                int cb = 2 * ks2 + hf;
                float b0 = biasS[cb * 8 + cn], b1 = biasS[cb * 8 + cn + 1];
                float x0 = fmaxf(acc[cb][0] + b0, 0.f);
                float x1 = fmaxf(acc[cb][1] + b1, 0.f);
                float x2 = fmaxf(acc[cb][2] + b0, 0.f);
                float x3 = fmaxf(acc[cb][3] + b1, 0.f);
                split2(x0, x1, Hh[ks2][hf * 2],     Hl[ks2][hf * 2]);
                split2(x2, x3, Hh[ks2][hf * 2 + 1], Hl[ks2][hf * 2 + 1]);
            }
        }
    }

    // ---- eGEMM: vacc = R(K=64) @ pm_w2^T ----
    float vacc[8][4];
    #pragma unroll
    for (int db = 0; db < 8; db++)
        #pragma unroll
        for (int e = 0; e < 4; e++) vacc[db][e] = 0.f;
    for (int ks = 0; ks < 4; ks++) {
        uint32_t ah[4], al[4];
        uint32_t aa = sb + OFF_A1H + (uint32_t)(arow * 136 + ks * 16 + asel) * 2;
        ldsm_x4(ah[0], ah[1], ah[2], ah[3], aa);
        aa = sb + OFF_A1L + (uint32_t)(arow * 136 + ks * 16 + asel) * 2;
        ldsm_x4(al[0], al[1], al[2], al[3], aa);
        #pragma unroll
        for (int db = 0; db < 8; db++) {
            uint32_t bh[2], bl[2];
            uint32_t ba = (uint32_t)((db * 8 + brow) * 72 + ks * 16 + bsel) * 2;
            ldsm_x2(bh[0], bh[1], sb + OFF_B3H + ba);
            ldsm_x2(bl[0], bl[1], sb + OFF_B3L + ba);
            mma16816(vacc[db], ah, bh);
            mma16816(vacc[db], ah, bl);
            mma16816(vacc[db], al, bh);
        }
    }
    // val = vacc + pm_b2 + v_j
    const int jr = w * 16 + (lane >> 2);
    #pragma unroll
    for (int db = 0; db < 8; db++) {
        int d0 = db * 8 + cn;
        float2 pb = *(const float2*)&pm_b2[d0];
        float2 v0 = *(const float2*)&g_v[(base + jr) * 64 + d0];
        float2 v1 = *(const float2*)&g_v[(base + jr + 8) * 64 + d0];
        vacc[db][0] += pb.x + v0.x;
        vacc[db][1] += pb.y + v0.y;
        vacc[db][2] += pb.x + v1.x;
        vacc[db][3] += pb.y + v1.y;
    }
    __syncthreads();   // all A1/W1/B3 reads done

    // ---- copy W2 into freed A1 region ----
    {
        const float4* s; float4* d;
        // W2h/W2l: 64*264 halfs = 33792 B = 2112 float4 = 8*256 + 64
        s = (const float4*)g_W2h; d = (float4*)(smem + OFF_W2H);
        #pragma unroll
        for (int q = 0; q < 8; q++) d[q * 256 + t] = s[q * 256 + t];
        if (t < 64) d[2048 + t] = s[2048 + t];
        s = (const float4*)g_W2l; d = (float4*)(smem + OFF_W2L);
        #pragma unroll
        for (int q = 0; q < 8; q++) d[q * 256 + t] = s[q * 256 + t];
        if (t < 64) d[2048 + t] = s[2048 + t];
    }
    __syncthreads();

    // ---- stash val into V_s (frees regs for GEMM2) ----
    {
        float* V_s = (float*)(smem + OFF_VS);
        #pragma unroll
        for (int db = 0; db < 8; db++) {
            int d0 = db * 8 + cn;
            V_s[d0 * 136 + jr]           = vacc[db][0];
            V_s[(d0 + 1) * 136 + jr]     = vacc[db][1];
            V_s[d0 * 136 + jr + 8]       = vacc[db][2];
            V_s[(d0 + 1) * 136 + jr + 8] = vacc[db][3];
        }
    }

    // ---- GEMM2: oacc = H(K=256) @ am_w2^T ----
    float oacc[8][4];
    #pragma unroll
    for (int db = 0; db < 8; db++)
        #pragma unroll
        for (int e = 0; e < 4; e++) oacc[db][e] = 0.f;
    #pragma unroll
    for (int ks2 = 0; ks2 < 16; ks2++) {
        #pragma unroll
        for (int db = 0; db < 8; db++) {
            uint32_t bh[2], bl[2];
            uint32_t ba = (uint32_t)((db * 8 + brow) * 264 + ks2 * 16 + bsel) * 2;
            ldsm_x2(bh[0], bh[1], sb + OFF_W2H + ba);
            ldsm_x2(bl[0], bl[1], sb + OFF_W2L + ba);
            mma16816(oacc[db], Hh[ks2], bh);
            mma16816(oacc[db], Hh[ks2], bl);
            mma16816(oacc[db], Hl[ks2], bh);
        }
    }
    // O (+am_b2) -> smem transposed [d][j]
    {
        float* O_s = (float*)(smem + OFF_OS);
        #pragma unroll
        for (int db = 0; db < 8; db++) {
            int d0 = db * 8 + cn;
            float2 ab = *(const float2*)&am_b2[d0];
            O_s[d0 * 136 + jr]           = oacc[db][0] + ab.x;
            O_s[(d0 + 1) * 136 + jr]     = oacc[db][1] + ab.y;
            O_s[d0 * 136 + jr + 8]       = oacc[db][2] + ab.x;
            O_s[(d0 + 1) * 136 + jr + 8] = oacc[db][3] + ab.y;
        }
    }
    __syncthreads();

    // ---- softmax over j per d ----
    {
        const int d = t & 63, jq = t >> 6;
        const float* O_s = (const float*)(smem + OFF_OS) + d * 136 + jq * 32;
        const float* V_s = (const float*)(smem + OFF_VS) + d * 136 + jq * 32;
        float ov[32], vv[32];
        #pragma unroll
        for (int q = 0; q < 8; q++) {
            float4 o4 = ((const float4*)O_s)[q];
            float4 v4 = ((const float4*)V_s)[q];
            ov[q * 4] = o4.x; ov[q * 4 + 1] = o4.y; ov[q * 4 + 2] = o4.z; ov[q * 4 + 3] = o4.w;
            vv[q * 4] = v4.x; vv[q * 4 + 1] = v4.y; vv[q * 4 + 2] = v4.z; vv[q * 4 + 3] = v4.w;
        }
        float m = ov[0];
        #pragma unroll
        for (int q = 1; q < 32; q++) m = fmaxf(m, ov[q]);
        float l = 0.f, a = 0.f;
        #pragma unroll
        for (int q = 0; q < 32; q++) {
            float p = __expf(ov[q] - m);
            l += p;
            a = fmaf(p, vv[q], a);
        }
        float* pm_ = (float*)(smem + OFF_RED);
        float* pl_ = pm_ + 256;
        float* pa_ = pm_ + 512;
        pm_[jq * 64 + d] = m;
        pl_[jq * 64 + d] = l;
        pa_[jq * 64 + d] = a;
        __syncthreads();
        if (t < 64) {
            float m0 = pm_[t], m1 = pm_[64 + t], m2 = pm_[128 + t], m3 = pm_[192 + t];
            float M = fmaxf(fmaxf(m0, m1), fmaxf(m2, m3));
            float e0 = __expf(m0 - M), e1 = __expf(m1 - M);
            float e2 = __expf(m2 - M), e3 = __expf(m3 - M);
            float L = pl_[t] * e0 + pl_[64 + t] * e1 + pl_[128 + t] * e2 + pl_[192 + t] * e3;
            float A = pa_[t] * e0 + pa_[64 + t] * e1 + pa_[128 + t] * e2 + pa_[192 + t] * e3;
            out[rowi * 64 + t] = A / L;
        }
    }
}

// ---------------- launch ----------------
extern "C" void kernel_launch(void* const* d_in, const int* in_sizes, int n_in,
                              void* d_out, int out_size) {
    const float* x      = (const float*)d_in[0];
    const float* pos    = (const float*)d_in[1];
    const float* w_qkv  = (const float*)d_in[2];
    const float* pm_w1  = (const float*)d_in[3];
    const float* pm_b1  = (const float*)d_in[4];
    const float* pm_w2  = (const float*)d_in[5];
    const float* pm_b2  = (const float*)d_in[6];
    const float* am_w1  = (const float*)d_in[7];
    const float* am_b1  = (const float*)d_in[8];
    const float* am_w2  = (const float*)d_in[9];
    const float* am_b2  = (const float*)d_in[10];
    float* out = (float*)d_out;

    static bool attr_set = false;
    if (!attr_set) {
        cudaFuncSetAttribute(pt_main, cudaFuncAttributeMaxDynamicSharedMemorySize, SMEM_TOTAL);
        attr_set = true;
    }

    prep_weights1<<<65, 256>>>(pm_w2, am_w1, am_b1, pm_b2);
    prep_weights2<<<208, 256>>>(am_w1, am_w2, pm_w2);
    prep_rows<<<BT * NPTS, 256>>>(x, pos, w_qkv, pm_w1);
    pt_main<<<dim3(NPTS, BT), 256, SMEM_TOTAL>>>(pm_b1, pm_b2, am_b2, out);
}